// round 5
// baseline (speedup 1.0000x reference)
#include <cuda_runtime.h>
#include <math.h>

#define NN 10000
#define NE 160000
#define HH 128
#define ER 20
#define RST 24                 // padded rbf stride (floats), 96B -> 16B aligned
#define CUTOFF_F 5.0f
#define PI_F 3.14159265358979323846f

typedef unsigned long long u64;

// ---------------- device scratch (static, no allocation) ----------------
__device__ float g_ns [NN*HH];
__device__ float g_nvA[NN*3*HH];
__device__ float g_nvB[NN*3*HH];
__device__ float g_so [NN*3*HH];
__device__ float g_Uv [NN*3*HH];
__device__ float g_Vv [NN*3*HH];
__device__ __align__(16) float g_prbfc[NE*RST];
__device__ float4 g_pgeo[NE];
__device__ int   g_psrc[NE];
__device__ int   g_deg [NN];
__device__ int   g_off [NN+1];
__device__ int   g_cur [NN];
__device__ int   g_perm[NE];

__device__ __forceinline__ float silu_f(float x){
    return x * (1.0f / (1.0f + __expf(-x)));
}
__device__ __forceinline__ u64 f2fma(u64 a, u64 b, u64 c){
    u64 d; asm("fma.rn.f32x2 %0, %1, %2, %3;" : "=l"(d) : "l"(a), "l"(b), "l"(c)); return d;
}
__device__ __forceinline__ u64 f2pack(float lo, float hi){
    u64 d; asm("mov.b64 %0, {%1, %2};" : "=l"(d) : "f"(lo), "f"(hi)); return d;
}
__device__ __forceinline__ float f2sum(u64 a){
    float x, y; asm("mov.b64 {%0, %1}, %2;" : "=f"(x), "=f"(y) : "l"(a)); return x + y;
}

// ---------------- setup kernels ----------------
__global__ void k_init_ns(const int* __restrict__ z, const float* __restrict__ embed){
    int i = blockIdx.x*blockDim.x + threadIdx.x;
    if (i < NN*HH){ int n = i >> 7; int j = i & 127; g_ns[i] = embed[z[n]*HH + j]; }
}
__global__ void k_zero_nv(){
    int i = blockIdx.x*blockDim.x + threadIdx.x;
    if (i < NN*3*HH) g_nvA[i] = 0.0f;
}
__global__ void k_zero_deg(){
    int i = blockIdx.x*blockDim.x + threadIdx.x;
    if (i < NN) g_deg[i] = 0;
}
__global__ void k_count(const int* __restrict__ edge){
    int e = blockIdx.x*blockDim.x + threadIdx.x;
    if (e < NE) atomicAdd(&g_deg[edge[2*e]], 1);
}
__global__ void k_scan(){
    __shared__ int sm[1024];
    __shared__ int base_s;
    int t = threadIdx.x;
    if (t == 0){ base_s = 0; g_off[0] = 0; }
    __syncthreads();
    for (int c0 = 0; c0 < NN; c0 += 1024){
        int i = c0 + t;
        int v = (i < NN) ? g_deg[i] : 0;
        sm[t] = v;
        __syncthreads();
        for (int ofs = 1; ofs < 1024; ofs <<= 1){
            int tv = (t >= ofs) ? sm[t-ofs] : 0;
            __syncthreads();
            sm[t] += tv;
            __syncthreads();
        }
        int inc = sm[t];
        int b = base_s;
        if (i < NN){ g_off[i+1] = b + inc; g_cur[i] = b + inc - v; }
        __syncthreads();
        if (t == 1023) base_s = b + sm[1023];
        __syncthreads();
    }
}
__global__ void k_scatter(const int* __restrict__ edge){
    int e = blockIdx.x*blockDim.x + threadIdx.x;
    if (e < NE){ int dst = edge[2*e]; int p = atomicAdd(&g_cur[dst], 1); g_perm[p] = e; }
}
__global__ void k_geom(const int* __restrict__ edge,
                       const float* __restrict__ dist, const float* __restrict__ diff){
    int p = blockIdx.x*blockDim.x + threadIdx.x;
    if (p >= NE) return;
    int e = g_perm[p];
    g_psrc[p] = edge[2*e + 1];
    float d = dist[e];
    float invd = 1.0f / d;
    float fc = (d < CUTOFF_F) ? 0.5f*(cosf(PI_F*d*(1.0f/CUTOFF_F)) + 1.0f) : 0.0f;
    g_pgeo[p] = make_float4(diff[3*e]*invd, diff[3*e+1]*invd, diff[3*e+2]*invd, fc);
    float s = fc * invd;
#pragma unroll
    for (int k = 0; k < ER; k++)
        g_prbfc[p*RST + k] = sinf(d * (float)(k+1) * (PI_F/CUTOFF_F)) * s;
#pragma unroll
    for (int k = ER; k < RST; k++) g_prbfc[p*RST + k] = 0.0f;
}

// ---------------- GEMM kernels: 256 thr, NB=32 tile, 2 cols/thread ----------------

// scalar_out = silu(ns@w1+b1)@w2+b2   [NN, 384]   grid 313
__global__ __launch_bounds__(256) void k_msg_mlp(int l,
        const float* __restrict__ w1_, const float* __restrict__ b1_,
        const float* __restrict__ w2_, const float* __restrict__ b2_){
    const float* w1 = w1_ + l*HH*HH;
    const float* b1 = b1_ + l*HH;
    const float* w2 = w2_ + l*HH*3*HH;
    const float* b2 = b2_ + l*3*HH;
    const int NB = 32, NH = 8;
    __shared__ __align__(16) float As[NB*HH];
    __shared__ __align__(16) float Hs[NB*HH];
    int tid = threadIdx.x;
    int c  = tid & 63;            // column thread
    int j0 = c, j1 = c + 64;
    int b0 = (tid >> 6) * NH;     // node group base within tile
    int n0 = blockIdx.x * NB;
    for (int t = tid; t < NB*HH; t += 256){
        int row = n0 + (t >> 7);
        if (row >= NN) row = NN - 1;
        As[t] = g_ns[row*HH + (t & 127)];
    }
    __syncthreads();
    u64 acc0[NH], acc1[NH];
#pragma unroll
    for (int i = 0; i < NH; i++){ acc0[i] = 0ULL; acc1[i] = 0ULL; }
    for (int k = 0; k < HH; k += 8){
        u64 p0 = f2pack(w1[(k+0)*HH+j0], w1[(k+1)*HH+j0]);
        u64 p1 = f2pack(w1[(k+2)*HH+j0], w1[(k+3)*HH+j0]);
        u64 p2 = f2pack(w1[(k+4)*HH+j0], w1[(k+5)*HH+j0]);
        u64 p3 = f2pack(w1[(k+6)*HH+j0], w1[(k+7)*HH+j0]);
        u64 q0 = f2pack(w1[(k+0)*HH+j1], w1[(k+1)*HH+j1]);
        u64 q1 = f2pack(w1[(k+2)*HH+j1], w1[(k+3)*HH+j1]);
        u64 q2 = f2pack(w1[(k+4)*HH+j1], w1[(k+5)*HH+j1]);
        u64 q3 = f2pack(w1[(k+6)*HH+j1], w1[(k+7)*HH+j1]);
#pragma unroll
        for (int i = 0; i < NH; i++){
            ulonglong2 a0 = *(const ulonglong2*)&As[(b0+i)*HH + k];
            ulonglong2 a1 = *(const ulonglong2*)&As[(b0+i)*HH + k + 4];
            acc0[i] = f2fma(a0.x, p0, acc0[i]);
            acc1[i] = f2fma(a0.x, q0, acc1[i]);
            acc0[i] = f2fma(a0.y, p1, acc0[i]);
            acc1[i] = f2fma(a0.y, q1, acc1[i]);
            acc0[i] = f2fma(a1.x, p2, acc0[i]);
            acc1[i] = f2fma(a1.x, q2, acc1[i]);
            acc0[i] = f2fma(a1.y, p3, acc0[i]);
            acc1[i] = f2fma(a1.y, q3, acc1[i]);
        }
    }
    float bb0 = b1[j0], bb1 = b1[j1];
#pragma unroll
    for (int i = 0; i < NH; i++){
        Hs[(b0+i)*HH + j0] = silu_f(f2sum(acc0[i]) + bb0);
        Hs[(b0+i)*HH + j1] = silu_f(f2sum(acc1[i]) + bb1);
    }
    __syncthreads();
    for (int g = 0; g < 3; g++){
        const float* wb = w2 + g*HH;
#pragma unroll
        for (int i = 0; i < NH; i++){ acc0[i] = 0ULL; acc1[i] = 0ULL; }
        for (int k = 0; k < HH; k += 8){
            u64 p0 = f2pack(wb[(k+0)*384+j0], wb[(k+1)*384+j0]);
            u64 p1 = f2pack(wb[(k+2)*384+j0], wb[(k+3)*384+j0]);
            u64 p2 = f2pack(wb[(k+4)*384+j0], wb[(k+5)*384+j0]);
            u64 p3 = f2pack(wb[(k+6)*384+j0], wb[(k+7)*384+j0]);
            u64 q0 = f2pack(wb[(k+0)*384+j1], wb[(k+1)*384+j1]);
            u64 q1 = f2pack(wb[(k+2)*384+j1], wb[(k+3)*384+j1]);
            u64 q2 = f2pack(wb[(k+4)*384+j1], wb[(k+5)*384+j1]);
            u64 q3 = f2pack(wb[(k+6)*384+j1], wb[(k+7)*384+j1]);
#pragma unroll
            for (int i = 0; i < NH; i++){
                ulonglong2 a0 = *(const ulonglong2*)&Hs[(b0+i)*HH + k];
                ulonglong2 a1 = *(const ulonglong2*)&Hs[(b0+i)*HH + k + 4];
                acc0[i] = f2fma(a0.x, p0, acc0[i]);
                acc1[i] = f2fma(a0.x, q0, acc1[i]);
                acc0[i] = f2fma(a0.y, p1, acc0[i]);
                acc1[i] = f2fma(a0.y, q1, acc1[i]);
                acc0[i] = f2fma(a1.x, p2, acc0[i]);
                acc1[i] = f2fma(a1.x, q2, acc1[i]);
                acc0[i] = f2fma(a1.y, p3, acc0[i]);
                acc1[i] = f2fma(a1.y, q3, acc1[i]);
            }
        }
        float bo0 = b2[g*HH + j0], bo1 = b2[g*HH + j1];
#pragma unroll
        for (int i = 0; i < NH; i++){
            int n = n0 + b0 + i;
            if (n < NN){
                g_so[(long)n*384 + g*HH + j0] = f2sum(acc0[i]) + bo0;
                g_so[(long)n*384 + g*HH + j1] = f2sum(acc1[i]) + bo1;
            }
        }
    }
}

// gather-based message pass over permuted streams
__global__ __launch_bounds__(128) void k_edge(int l,
        const float* __restrict__ fw_, const float* __restrict__ fb_){
    const float* Wf = fw_ + l*ER*3*HH;
    const float* Bf = fb_ + l*3*HH;
    const float* nv_in  = (l == 1) ? g_nvB : g_nvA;
    float*       nv_out = (l == 1) ? g_nvA : g_nvB;
    int j = threadIdx.x;
    u64 wf0[ER/2], wf1[ER/2], wf2[ER/2];
#pragma unroll
    for (int k = 0; k < ER/2; k++){
        wf0[k] = f2pack(Wf[(2*k)*384 + j],       Wf[(2*k+1)*384 + j]);
        wf1[k] = f2pack(Wf[(2*k)*384 + 128 + j], Wf[(2*k+1)*384 + 128 + j]);
        wf2[k] = f2pack(Wf[(2*k)*384 + 256 + j], Wf[(2*k+1)*384 + 256 + j]);
    }
    float bf0 = Bf[j], bf1 = Bf[128+j], bf2 = Bf[256+j];
    const int NPB = 4;
    for (int ni = 0; ni < NPB; ni++){
        int n = blockIdx.x*NPB + ni;
        int s = g_off[n], e1 = g_off[n+1];
        float acc_s = 0.f, av0 = 0.f, av1 = 0.f, av2 = 0.f;
        for (int p = s; p < e1; p++){
            int src = g_psrc[p];
            float4 geo = g_pgeo[p];
            float fc = geo.w;
            u64 f0a = f2pack(bf0*fc, 0.f);
            u64 f1a = f2pack(bf1*fc, 0.f);
            u64 f2a = f2pack(bf2*fc, 0.f);
            const ulonglong2* r2 = (const ulonglong2*)&g_prbfc[p*RST];
#pragma unroll
            for (int q = 0; q < 5; q++){
                ulonglong2 rr = r2[q];        // lanes = (r[4q],r[4q+1]) and (r[4q+2],r[4q+3])
                f0a = f2fma(rr.x, wf0[2*q],   f0a);
                f0a = f2fma(rr.y, wf0[2*q+1], f0a);
                f1a = f2fma(rr.x, wf1[2*q],   f1a);
                f1a = f2fma(rr.y, wf1[2*q+1], f1a);
                f2a = f2fma(rr.x, wf2[2*q],   f2a);
                f2a = f2fma(rr.y, wf2[2*q+1], f2a);
            }
            const float* sb = &g_so[(long)src*384];
            float gsv = f2sum(f0a) * sb[j];
            float gev = f2sum(f1a) * sb[128 + j];
            float ms  = f2sum(f2a) * sb[256 + j];
            acc_s += ms;
            const float* nb = &nv_in[(long)src*384];
            av0 += nb[j      ]*gsv + gev*geo.x;
            av1 += nb[128 + j]*gsv + gev*geo.y;
            av2 += nb[256 + j]*gsv + gev*geo.z;
        }
        g_ns[n*128 + j] += acc_s;
        nv_out[(long)n*384 + j      ] = nv_in[(long)n*384 + j      ] + av0;
        nv_out[(long)n*384 + 128 + j] = nv_in[(long)n*384 + 128 + j] + av1;
        nv_out[(long)n*384 + 256 + j] = nv_in[(long)n*384 + 256 + j] + av2;
    }
}

// Uv/Vv GEMM: already 2-output amortized; grid 1875, 256 thr
__global__ __launch_bounds__(256) void k_uv(int l,
        const float* __restrict__ wU_, const float* __restrict__ bU_,
        const float* __restrict__ wV_, const float* __restrict__ bV_){
    const float* wU = wU_ + l*HH*HH; const float* bU = bU_ + l*HH;
    const float* wV = wV_ + l*HH*HH; const float* bV = bV_ + l*HH;
    const float* nv = (l == 1) ? g_nvA : g_nvB;
    const int NB = 16, NH = 8;
    __shared__ __align__(16) float As[NB*HH];
    int tid = threadIdx.x;
    int j = tid & 127;
    int b0 = (tid >> 7) * NH;
    int r0 = blockIdx.x * NB;
    for (int t = tid; t < NB*HH; t += 256) As[t] = nv[(long)r0*HH + t];
    __syncthreads();
    u64 aU[NH], aV[NH];
#pragma unroll
    for (int i = 0; i < NH; i++){ aU[i] = 0ULL; aV[i] = 0ULL; }
    for (int k = 0; k < HH; k += 8){
        u64 pu0 = f2pack(wU[(k+0)*HH+j], wU[(k+1)*HH+j]);
        u64 pu1 = f2pack(wU[(k+2)*HH+j], wU[(k+3)*HH+j]);
        u64 pu2 = f2pack(wU[(k+4)*HH+j], wU[(k+5)*HH+j]);
        u64 pu3 = f2pack(wU[(k+6)*HH+j], wU[(k+7)*HH+j]);
        u64 pv0 = f2pack(wV[(k+0)*HH+j], wV[(k+1)*HH+j]);
        u64 pv1 = f2pack(wV[(k+2)*HH+j], wV[(k+3)*HH+j]);
        u64 pv2 = f2pack(wV[(k+4)*HH+j], wV[(k+5)*HH+j]);
        u64 pv3 = f2pack(wV[(k+6)*HH+j], wV[(k+7)*HH+j]);
#pragma unroll
        for (int i = 0; i < NH; i++){
            ulonglong2 a0 = *(const ulonglong2*)&As[(b0+i)*HH + k];
            ulonglong2 a1 = *(const ulonglong2*)&As[(b0+i)*HH + k + 4];
            aU[i] = f2fma(a0.x, pu0, aU[i]);
            aV[i] = f2fma(a0.x, pv0, aV[i]);
            aU[i] = f2fma(a0.y, pu1, aU[i]);
            aV[i] = f2fma(a0.y, pv1, aV[i]);
            aU[i] = f2fma(a1.x, pu2, aU[i]);
            aV[i] = f2fma(a1.x, pv2, aV[i]);
            aU[i] = f2fma(a1.y, pu3, aU[i]);
            aV[i] = f2fma(a1.y, pv3, aV[i]);
        }
    }
    float bu = bU[j], bv = bV[j];
#pragma unroll
    for (int i = 0; i < NH; i++){
        g_Uv[(long)(r0+b0+i)*HH + j] = f2sum(aU[i]) + bu;
        g_Vv[(long)(r0+b0+i)*HH + j] = f2sum(aV[i]) + bv;
    }
}

// update MLP + apply   grid 313, 256 thr, NB=32, 2 cols/thread
__global__ __launch_bounds__(256) void k_upd(int l,
        const float* __restrict__ w1_, const float* __restrict__ b1_,
        const float* __restrict__ w2_, const float* __restrict__ b2_){
    const float* w1 = w1_ + l*2*HH*HH; const float* b1 = b1_ + l*HH;
    const float* w2 = w2_ + l*HH*3*HH; const float* b2 = b2_ + l*3*HH;
    float* nv = (l == 1) ? g_nvA : g_nvB;
    const int NB = 32, NH = 8;
    __shared__ __align__(16) float Ms[NB*2*HH];
    __shared__ __align__(16) float Hs[NB*HH];
    int tid = threadIdx.x;
    int c  = tid & 63;
    int j0 = c, j1 = c + 64;
    int b0 = (tid >> 6) * NH;
    int n0 = blockIdx.x * NB;
    // fill Ms rows (each thread covers 2 cols x NH rows in the 256-wide Ms)
#pragma unroll
    for (int i = 0; i < NH; i++){
        int n = n0 + b0 + i; if (n >= NN) n = NN - 1;
#pragma unroll
        for (int jj = 0; jj < 2; jj++){
            int j = jj ? j1 : j0;
            float v0 = g_Vv[(long)n*384 + j];
            float v1 = g_Vv[(long)n*384 + 128 + j];
            float v2 = g_Vv[(long)n*384 + 256 + j];
            Ms[(b0+i)*256 + j]       = sqrtf(v0*v0 + v1*v1 + v2*v2);
            Ms[(b0+i)*256 + 128 + j] = g_ns[n*128 + j];
        }
    }
    __syncthreads();
    u64 acc0[NH], acc1[NH];
#pragma unroll
    for (int i = 0; i < NH; i++){ acc0[i] = 0ULL; acc1[i] = 0ULL; }
    for (int k = 0; k < 2*HH; k += 8){
        u64 p0 = f2pack(w1[(k+0)*HH+j0], w1[(k+1)*HH+j0]);
        u64 p1 = f2pack(w1[(k+2)*HH+j0], w1[(k+3)*HH+j0]);
        u64 p2 = f2pack(w1[(k+4)*HH+j0], w1[(k+5)*HH+j0]);
        u64 p3 = f2pack(w1[(k+6)*HH+j0], w1[(k+7)*HH+j0]);
        u64 q0 = f2pack(w1[(k+0)*HH+j1], w1[(k+1)*HH+j1]);
        u64 q1 = f2pack(w1[(k+2)*HH+j1], w1[(k+3)*HH+j1]);
        u64 q2 = f2pack(w1[(k+4)*HH+j1], w1[(k+5)*HH+j1]);
        u64 q3 = f2pack(w1[(k+6)*HH+j1], w1[(k+7)*HH+j1]);
#pragma unroll
        for (int i = 0; i < NH; i++){
            ulonglong2 a0 = *(const ulonglong2*)&Ms[(b0+i)*256 + k];
            ulonglong2 a1 = *(const ulonglong2*)&Ms[(b0+i)*256 + k + 4];
            acc0[i] = f2fma(a0.x, p0, acc0[i]);
            acc1[i] = f2fma(a0.x, q0, acc1[i]);
            acc0[i] = f2fma(a0.y, p1, acc0[i]);
            acc1[i] = f2fma(a0.y, q1, acc1[i]);
            acc0[i] = f2fma(a1.x, p2, acc0[i]);
            acc1[i] = f2fma(a1.x, q2, acc1[i]);
            acc0[i] = f2fma(a1.y, p3, acc0[i]);
            acc1[i] = f2fma(a1.y, q3, acc1[i]);
        }
    }
    float bb0 = b1[j0], bb1 = b1[j1];
#pragma unroll
    for (int i = 0; i < NH; i++){
        Hs[(b0+i)*HH + j0] = silu_f(f2sum(acc0[i]) + bb0);
        Hs[(b0+i)*HH + j1] = silu_f(f2sum(acc1[i]) + bb1);
    }
    __syncthreads();
    float gate0[3][NH], gate1[3][NH];
    for (int g = 0; g < 3; g++){
        const float* wb = w2 + g*HH;
#pragma unroll
        for (int i = 0; i < NH; i++){ acc0[i] = 0ULL; acc1[i] = 0ULL; }
        for (int k = 0; k < HH; k += 8){
            u64 p0 = f2pack(wb[(k+0)*384+j0], wb[(k+1)*384+j0]);
            u64 p1 = f2pack(wb[(k+2)*384+j0], wb[(k+3)*384+j0]);
            u64 p2 = f2pack(wb[(k+4)*384+j0], wb[(k+5)*384+j0]);
            u64 p3 = f2pack(wb[(k+6)*384+j0], wb[(k+7)*384+j0]);
            u64 q0 = f2pack(wb[(k+0)*384+j1], wb[(k+1)*384+j1]);
            u64 q1 = f2pack(wb[(k+2)*384+j1], wb[(k+3)*384+j1]);
            u64 q2 = f2pack(wb[(k+4)*384+j1], wb[(k+5)*384+j1]);
            u64 q3 = f2pack(wb[(k+6)*384+j1], wb[(k+7)*384+j1]);
#pragma unroll
            for (int i = 0; i < NH; i++){
                ulonglong2 a0 = *(const ulonglong2*)&Hs[(b0+i)*HH + k];
                ulonglong2 a1 = *(const ulonglong2*)&Hs[(b0+i)*HH + k + 4];
                acc0[i] = f2fma(a0.x, p0, acc0[i]);
                acc1[i] = f2fma(a0.x, q0, acc1[i]);
                acc0[i] = f2fma(a0.y, p1, acc0[i]);
                acc1[i] = f2fma(a0.y, q1, acc1[i]);
                acc0[i] = f2fma(a1.x, p2, acc0[i]);
                acc1[i] = f2fma(a1.x, q2, acc1[i]);
                acc0[i] = f2fma(a1.y, p3, acc0[i]);
                acc1[i] = f2fma(a1.y, q3, acc1[i]);
            }
        }
        float bo0 = b2[g*HH + j0], bo1 = b2[g*HH + j1];
#pragma unroll
        for (int i = 0; i < NH; i++){
            gate0[g][i] = f2sum(acc0[i]) + bo0;
            gate1[g][i] = f2sum(acc1[i]) + bo1;
        }
    }
#pragma unroll
    for (int i = 0; i < NH; i++){
        int n = n0 + b0 + i;
        if (n >= NN) continue;
#pragma unroll
        for (int jj = 0; jj < 2; jj++){
            int j = jj ? j1 : j0;
            float avv = jj ? gate1[0][i] : gate0[0][i];
            float asv = jj ? gate1[1][i] : gate0[1][i];
            float ass = jj ? gate1[2][i] : gate0[2][i];
            float U0 = g_Uv[(long)n*384 + j], U1 = g_Uv[(long)n*384 + 128 + j], U2 = g_Uv[(long)n*384 + 256 + j];
            float V0 = g_Vv[(long)n*384 + j], V1 = g_Vv[(long)n*384 + 128 + j], V2 = g_Vv[(long)n*384 + 256 + j];
            float duv = U0*V0 + U1*V1 + U2*V2;
            nv[(long)n*384 + j      ] += avv*U0;
            nv[(long)n*384 + 128 + j] += avv*U1;
            nv[(long)n*384 + 256 + j] += avv*U2;
            g_ns[n*128 + j] += asv*duv + ass;
        }
    }
}

// readout   grid 313, 256 thr, NB=32, 2 cols/thread
__global__ __launch_bounds__(256) void k_readout(
        const float* __restrict__ w1, const float* __restrict__ b1,
        const float* __restrict__ w2, const float* __restrict__ b2,
        float* __restrict__ out){
    const int NB = 32, NH = 8;
    __shared__ __align__(16) float As[NB*HH];
    __shared__ __align__(16) float Hs[NB*HH];
    int tid = threadIdx.x;
    int c  = tid & 63;
    int j0 = c, j1 = c + 64;
    int b0 = (tid >> 6) * NH;
    int n0 = blockIdx.x * NB;
    for (int t = tid; t < NB*HH; t += 256){
        int row = n0 + (t >> 7);
        if (row >= NN) row = NN - 1;
        As[t] = g_ns[row*HH + (t & 127)];
    }
    __syncthreads();
    u64 acc0[NH], acc1[NH];
#pragma unroll
    for (int i = 0; i < NH; i++){ acc0[i] = 0ULL; acc1[i] = 0ULL; }
    for (int k = 0; k < HH; k += 8){
        u64 p0 = f2pack(w1[(k+0)*HH+j0], w1[(k+1)*HH+j0]);
        u64 p1 = f2pack(w1[(k+2)*HH+j0], w1[(k+3)*HH+j0]);
        u64 p2 = f2pack(w1[(k+4)*HH+j0], w1[(k+5)*HH+j0]);
        u64 p3 = f2pack(w1[(k+6)*HH+j0], w1[(k+7)*HH+j0]);
        u64 q0 = f2pack(w1[(k+0)*HH+j1], w1[(k+1)*HH+j1]);
        u64 q1 = f2pack(w1[(k+2)*HH+j1], w1[(k+3)*HH+j1]);
        u64 q2 = f2pack(w1[(k+4)*HH+j1], w1[(k+5)*HH+j1]);
        u64 q3 = f2pack(w1[(k+6)*HH+j1], w1[(k+7)*HH+j1]);
#pragma unroll
        for (int i = 0; i < NH; i++){
            ulonglong2 a0 = *(const ulonglong2*)&As[(b0+i)*HH + k];
            ulonglong2 a1 = *(const ulonglong2*)&As[(b0+i)*HH + k + 4];
            acc0[i] = f2fma(a0.x, p0, acc0[i]);
            acc1[i] = f2fma(a0.x, q0, acc1[i]);
            acc0[i] = f2fma(a0.y, p1, acc0[i]);
            acc1[i] = f2fma(a0.y, q1, acc1[i]);
            acc0[i] = f2fma(a1.x, p2, acc0[i]);
            acc1[i] = f2fma(a1.x, q2, acc1[i]);
            acc0[i] = f2fma(a1.y, p3, acc0[i]);
            acc1[i] = f2fma(a1.y, q3, acc1[i]);
        }
    }
    float bb0 = b1[j0], bb1 = b1[j1];
#pragma unroll
    for (int i = 0; i < NH; i++){
        Hs[(b0+i)*HH + j0] = silu_f(f2sum(acc0[i]) + bb0);
        Hs[(b0+i)*HH + j1] = silu_f(f2sum(acc1[i]) + bb1);
    }
    __syncthreads();
#pragma unroll
    for (int i = 0; i < NH; i++){ acc0[i] = 0ULL; acc1[i] = 0ULL; }
    for (int k = 0; k < HH; k += 8){
        u64 p0 = f2pack(w2[(k+0)*HH+j0], w2[(k+1)*HH+j0]);
        u64 p1 = f2pack(w2[(k+2)*HH+j0], w2[(k+3)*HH+j0]);
        u64 p2 = f2pack(w2[(k+4)*HH+j0], w2[(k+5)*HH+j0]);
        u64 p3 = f2pack(w2[(k+6)*HH+j0], w2[(k+7)*HH+j0]);
        u64 q0 = f2pack(w2[(k+0)*HH+j1], w2[(k+1)*HH+j1]);
        u64 q1 = f2pack(w2[(k+2)*HH+j1], w2[(k+3)*HH+j1]);
        u64 q2 = f2pack(w2[(k+4)*HH+j1], w2[(k+5)*HH+j1]);
        u64 q3 = f2pack(w2[(k+6)*HH+j1], w2[(k+7)*HH+j1]);
#pragma unroll
        for (int i = 0; i < NH; i++){
            ulonglong2 a0 = *(const ulonglong2*)&Hs[(b0+i)*HH + k];
            ulonglong2 a1 = *(const ulonglong2*)&Hs[(b0+i)*HH + k + 4];
            acc0[i] = f2fma(a0.x, p0, acc0[i]);
            acc1[i] = f2fma(a0.x, q0, acc1[i]);
            acc0[i] = f2fma(a0.y, p1, acc0[i]);
            acc1[i] = f2fma(a0.y, q1, acc1[i]);
            acc0[i] = f2fma(a1.x, p2, acc0[i]);
            acc1[i] = f2fma(a1.x, q2, acc1[i]);
            acc0[i] = f2fma(a1.y, p3, acc0[i]);
            acc1[i] = f2fma(a1.y, q3, acc1[i]);
        }
    }
    float b20 = b2[j0], b21 = b2[j1];
#pragma unroll
    for (int i = 0; i < NH; i++){
        int n = n0 + b0 + i;
        if (n < NN){
            out[(long)n*HH + j0] = f2sum(acc0[i]) + b20;
            out[(long)n*HH + j1] = f2sum(acc1[i]) + b21;
        }
    }
}

// ---------------- launch ----------------
extern "C" void kernel_launch(void* const* d_in, const int* in_sizes, int n_in,
                              void* d_out, int out_size){
    const int*   z         = (const int*)  d_in[0];
    const int*   edge      = (const int*)  d_in[1];
    const float* edge_diff = (const float*)d_in[2];
    const float* edge_dist = (const float*)d_in[3];
    const float* embed     = (const float*)d_in[4];
    const float* mfw = (const float*)d_in[5];
    const float* mfb = (const float*)d_in[6];
    const float* mw1 = (const float*)d_in[7];
    const float* mb1 = (const float*)d_in[8];
    const float* mw2 = (const float*)d_in[9];
    const float* mb2 = (const float*)d_in[10];
    const float* uUw = (const float*)d_in[11];
    const float* uUb = (const float*)d_in[12];
    const float* uVw = (const float*)d_in[13];
    const float* uVb = (const float*)d_in[14];
    const float* uw1 = (const float*)d_in[15];
    const float* ub1 = (const float*)d_in[16];
    const float* uw2 = (const float*)d_in[17];
    const float* ub2 = (const float*)d_in[18];
    const float* rw1 = (const float*)d_in[19];
    const float* rb1 = (const float*)d_in[20];
    const float* rw2 = (const float*)d_in[21];
    const float* rb2 = (const float*)d_in[22];
    float* out = (float*)d_out;

    const int GB = (NN + 31) / 32;   // 313

    // position 4 = k_msg_mlp(layer 0) so ncu's profile slot lands on the GEMM
    k_init_ns<<<(NN*HH + 255)/256, 256>>>(z, embed);
    k_zero_nv<<<(NN*3*HH + 255)/256, 256>>>();
    k_zero_deg<<<(NN + 255)/256, 256>>>();
    k_msg_mlp<<<GB, 256>>>(0, mw1, mb1, mw2, mb2);
    k_count<<<(NE + 255)/256, 256>>>(edge);
    k_scan<<<1, 1024>>>();
    k_scatter<<<(NE + 255)/256, 256>>>(edge);
    k_geom<<<(NE + 255)/256, 256>>>(edge, edge_dist, edge_diff);

    for (int l = 0; l < 3; l++){
        if (l > 0) k_msg_mlp<<<GB, 256>>>(l, mw1, mb1, mw2, mb2);
        k_edge<<<NN/4, 128>>>(l, mfw, mfb);
        k_uv<<<NN*3/16, 256>>>(l, uUw, uUb, uVw, uVb);
        k_upd<<<GB, 256>>>(l, uw1, ub1, uw2, ub2);
    }
    k_readout<<<GB, 256>>>(rw1, rb1, rw2, rb2, out);
}

// round 6
// speedup vs baseline: 1.3080x; 1.3080x over previous
#include <cuda_runtime.h>
#include <cuda_bf16.h>
#include <math.h>

#define NN 10000
#define NE 160000
#define HH 128
#define ER 20
#define RST 24
#define CUTOFF_F 5.0f
#define PI_F 3.14159265358979323846f

typedef unsigned long long u64;
typedef unsigned int u32;

// ---------------- device scratch ----------------
__device__ float g_ns [NN*HH];
__device__ float g_nvA[NN*3*HH];
__device__ float g_nvB[NN*3*HH];
__device__ float g_so [NN*3*HH];
__device__ float g_UV [NN*3*256];      // uv gemm out: rows (n,d), cols 0..127=Uv 128..255=Vv
__device__ float g_gate[NN*384];
__device__ __align__(16) float g_prbfc[NE*RST];
__device__ float4 g_pgeo[NE];
__device__ int   g_psrc[NE];
__device__ int   g_deg [NN];
__device__ int   g_off [NN+1];
__device__ int   g_cur [NN];
__device__ int   g_perm[NE];
// bf16 activation buffers (hi/lo)
__device__ __nv_bfloat16 g_a0h[NN*3*256];
__device__ __nv_bfloat16 g_a0l[NN*3*256];
__device__ __nv_bfloat16 g_a1h[NN*HH];
__device__ __nv_bfloat16 g_a1l[NN*HH];
// packed weight fragments (u64 per (kstep,n,m))
#define WP_TOTAL 143360
__device__ u64 g_wph[WP_TOTAL];
__device__ u64 g_wpl[WP_TOTAL];
// offsets (u64 units)
#define OFF_MSGW1 0L        // 3 x (8*128*4  = 4096)
#define OFF_MSGW2 12288L    // 3 x (8*384*4  = 12288)
#define OFF_UVW   49152L    // 3 x (8*256*4  = 8192)
#define OFF_UPDW1 73728L    // 3 x (16*128*4 = 8192)
#define OFF_UPDW2 98304L    // 3 x (8*384*4  = 12288)
#define OFF_ROW1  135168L
#define OFF_ROW2  139264L

__device__ __forceinline__ float silu_f(float x){
    return x * (1.0f / (1.0f + __expf(-x)));
}
__device__ __forceinline__ u64 f2fma(u64 a, u64 b, u64 c){
    u64 d; asm("fma.rn.f32x2 %0, %1, %2, %3;" : "=l"(d) : "l"(a), "l"(b), "l"(c)); return d;
}
__device__ __forceinline__ u64 f2pack(float lo, float hi){
    u64 d; asm("mov.b64 %0, {%1, %2};" : "=l"(d) : "f"(lo), "f"(hi)); return d;
}
__device__ __forceinline__ float f2sum(u64 a){
    float x, y; asm("mov.b64 {%0, %1}, %2;" : "=f"(x), "=f"(y) : "l"(a)); return x + y;
}
__device__ __forceinline__ void mma16816(float* c, u32 a0,u32 a1,u32 a2,u32 a3, u32 b0,u32 b1){
    asm volatile("mma.sync.aligned.m16n8k16.row.col.f32.bf16.bf16.f32 "
        "{%0,%1,%2,%3}, {%4,%5,%6,%7}, {%8,%9}, {%0,%1,%2,%3};"
        : "+f"(c[0]),"+f"(c[1]),"+f"(c[2]),"+f"(c[3])
        : "r"(a0),"r"(a1),"r"(a2),"r"(a3),"r"(b0),"r"(b1));
}

// ---------------- setup kernels ----------------
__global__ void k_init_ns(const int* __restrict__ z, const float* __restrict__ embed){
    int i = blockIdx.x*blockDim.x + threadIdx.x;
    if (i < NN*HH){ int n = i >> 7; int j = i & 127; g_ns[i] = embed[z[n]*HH + j]; }
}
__global__ void k_zero_nv(){
    int i = blockIdx.x*blockDim.x + threadIdx.x;
    if (i < NN*3*HH) g_nvA[i] = 0.0f;
}
__global__ void k_zero_deg(){
    int i = blockIdx.x*blockDim.x + threadIdx.x;
    if (i < NN) g_deg[i] = 0;
}
__global__ void k_count(const int* __restrict__ edge){
    int e = blockIdx.x*blockDim.x + threadIdx.x;
    if (e < NE) atomicAdd(&g_deg[edge[2*e]], 1);
}
__global__ void k_scan(){
    __shared__ int sm[1024];
    __shared__ int base_s;
    int t = threadIdx.x;
    if (t == 0){ base_s = 0; g_off[0] = 0; }
    __syncthreads();
    for (int c0 = 0; c0 < NN; c0 += 1024){
        int i = c0 + t;
        int v = (i < NN) ? g_deg[i] : 0;
        sm[t] = v;
        __syncthreads();
        for (int ofs = 1; ofs < 1024; ofs <<= 1){
            int tv = (t >= ofs) ? sm[t-ofs] : 0;
            __syncthreads();
            sm[t] += tv;
            __syncthreads();
        }
        int inc = sm[t];
        int b = base_s;
        if (i < NN){ g_off[i+1] = b + inc; g_cur[i] = b + inc - v; }
        __syncthreads();
        if (t == 1023) base_s = b + sm[1023];
        __syncthreads();
    }
}
__global__ void k_scatter(const int* __restrict__ edge){
    int e = blockIdx.x*blockDim.x + threadIdx.x;
    if (e < NE){ int dst = edge[2*e]; int p = atomicAdd(&g_cur[dst], 1); g_perm[p] = e; }
}
__global__ void k_geom(const int* __restrict__ edge,
                       const float* __restrict__ dist, const float* __restrict__ diff){
    int p = blockIdx.x*blockDim.x + threadIdx.x;
    if (p >= NE) return;
    int e = g_perm[p];
    g_psrc[p] = edge[2*e + 1];
    float d = dist[e];
    float invd = 1.0f / d;
    float fc = (d < CUTOFF_F) ? 0.5f*(cosf(PI_F*d*(1.0f/CUTOFF_F)) + 1.0f) : 0.0f;
    g_pgeo[p] = make_float4(diff[3*e]*invd, diff[3*e+1]*invd, diff[3*e+2]*invd, fc);
    float s = fc * invd;
#pragma unroll
    for (int k = 0; k < ER; k++)
        g_prbfc[p*RST + k] = sinf(d * (float)(k+1) * (PI_F/CUTOFF_F)) * s;
#pragma unroll
    for (int k = ER; k < RST; k++) g_prbfc[p*RST + k] = 0.0f;
}

// pack weights [L][K][N] (row-major, optional concat of two srcs along N at N1)
// into fragment-ready u64 streams at g_wph/g_wpl + dstoff.
__global__ void k_pack(const float* __restrict__ src, const float* __restrict__ src2,
                       int L, int K, int N, int N1, long dstoff){
    long per = (long)(K/16)*N*4;
    long tot = per * L;
    long i = (long)blockIdx.x*blockDim.x + threadIdx.x;
    if (i >= tot) return;
    int l = (int)(i / per); long r = i % per;
    int m = (int)(r & 3); long r2 = r >> 2;
    int n = (int)(r2 % N); int s = (int)(r2 / N);
    int k0 = s*16 + 2*m;
    const float* S; int nn, Nw;
    if (src2 && n >= N1){ S = src2 + (long)l*K*(N-N1); nn = n - N1; Nw = N - N1; }
    else if (src2)      { S = src  + (long)l*K*N1;     nn = n;      Nw = N1; }
    else                { S = src  + (long)l*K*N;      nn = n;      Nw = N; }
    float w0 = S[(long)(k0  )*Nw + nn];
    float w1 = S[(long)(k0+1)*Nw + nn];
    float w8 = S[(long)(k0+8)*Nw + nn];
    float w9 = S[(long)(k0+9)*Nw + nn];
    __nv_bfloat16 h0 = __float2bfloat16_rn(w0), h1 = __float2bfloat16_rn(w1);
    __nv_bfloat16 h8 = __float2bfloat16_rn(w8), h9 = __float2bfloat16_rn(w9);
    u32 hlo = (u32)__bfloat16_as_ushort(h0) | ((u32)__bfloat16_as_ushort(h1) << 16);
    u32 hhi = (u32)__bfloat16_as_ushort(h8) | ((u32)__bfloat16_as_ushort(h9) << 16);
    g_wph[dstoff + i] = (u64)hlo | ((u64)hhi << 32);
    __nv_bfloat16 l0 = __float2bfloat16_rn(w0 - __bfloat162float(h0));
    __nv_bfloat16 l1 = __float2bfloat16_rn(w1 - __bfloat162float(h1));
    __nv_bfloat16 l8 = __float2bfloat16_rn(w8 - __bfloat162float(h8));
    __nv_bfloat16 l9 = __float2bfloat16_rn(w9 - __bfloat162float(h9));
    u32 llo = (u32)__bfloat16_as_ushort(l0) | ((u32)__bfloat16_as_ushort(l1) << 16);
    u32 lhi = (u32)__bfloat16_as_ushort(l8) | ((u32)__bfloat16_as_ushort(l9) << 16);
    g_wpl[dstoff + i] = (u64)llo | ((u64)lhi << 32);
}

// convert fp32 activations -> bf16 hi/lo into A0.  src: 0=g_ns 1=g_nvA 2=g_nvB
__global__ void k_cvt_a(int src, long total){
    long i = (long)blockIdx.x*blockDim.x + threadIdx.x;
    if (i >= total) return;
    float x = (src == 0) ? g_ns[i] : (src == 1) ? g_nvA[i] : g_nvB[i];
    __nv_bfloat16 h = __float2bfloat16_rn(x);
    g_a0h[i] = h;
    g_a0l[i] = __float2bfloat16_rn(x - __bfloat162float(h));
}

// ---------------- generic tensor-core GEMM ----------------
// C[M,Ntot] = A @ W + bias ; block: 128 thr = 4 warps, tile 64 x 128
// asel: 0=A0, 1=A1.  mode 0: fp32 out (osel 0=g_so 1=g_UV 2=g_gate 3=Cext)
// mode 1: silu -> bf16 hi/lo into A1.
__global__ __launch_bounds__(128) void k_mma(
        long woff, int M, int K, int Ntot, int asel, int mode, int osel,
        const float* __restrict__ bias, const float* __restrict__ bias2,
        float* __restrict__ Cext){
    int tid = threadIdx.x;
    int lane = tid & 31, w = tid >> 5;
    int m0 = blockIdx.x*64 + w*16;
    int nbase = blockIdx.y*128;
    const __nv_bfloat16* Ah = asel ? g_a1h : g_a0h;
    const __nv_bfloat16* Al = asel ? g_a1l : g_a0l;
    int r0 = m0 + (lane >> 2);
    int r1 = r0 + 8;
    int r0c = r0 < M ? r0 : M-1;
    int r1c = r1 < M ? r1 : M-1;
    int kofs = (lane & 3)*2;
    const u64* WH = g_wph + woff;
    const u64* WL = g_wpl + woff;
    float c[16][4];
#pragma unroll
    for (int nt = 0; nt < 16; nt++){ c[nt][0]=0.f; c[nt][1]=0.f; c[nt][2]=0.f; c[nt][3]=0.f; }
    int nsteps = K >> 4;
    for (int s = 0; s < nsteps; s++){
        int k0 = s*16 + kofs;
        const __nv_bfloat16* ph0 = Ah + (long)r0c*K + k0;
        const __nv_bfloat16* ph1 = Ah + (long)r1c*K + k0;
        const __nv_bfloat16* pl0 = Al + (long)r0c*K + k0;
        const __nv_bfloat16* pl1 = Al + (long)r1c*K + k0;
        u32 ah0 = *(const u32*)(ph0);
        u32 ah1 = *(const u32*)(ph1);
        u32 ah2 = *(const u32*)(ph0 + 8);
        u32 ah3 = *(const u32*)(ph1 + 8);
        u32 al0 = *(const u32*)(pl0);
        u32 al1 = *(const u32*)(pl1);
        u32 al2 = *(const u32*)(pl0 + 8);
        u32 al3 = *(const u32*)(pl1 + 8);
        const u64* wb = WH + ((long)s*Ntot + nbase)*4 + (lane & 3);
        const u64* wbl = WL + ((long)s*Ntot + nbase)*4 + (lane & 3);
#pragma unroll
        for (int nt = 0; nt < 16; nt++){
            int wi = (nt*8 + (lane >> 2))*4;
            u64 wh = wb[wi];
            u64 wl = wbl[wi];
            u32 bh0 = (u32)wh, bh1 = (u32)(wh >> 32);
            u32 bl0 = (u32)wl, bl1 = (u32)(wl >> 32);
            mma16816(c[nt], ah0, ah1, ah2, ah3, bh0, bh1);
            mma16816(c[nt], al0, al1, al2, al3, bh0, bh1);
            mma16816(c[nt], ah0, ah1, ah2, ah3, bl0, bl1);
        }
    }
    // epilogue
    int colq = (lane & 3)*2;
#pragma unroll
    for (int nt = 0; nt < 16; nt++){
        int col = nbase + nt*8 + colq;
        float b0v, b1v;
        if (bias2 != 0 && col >= 128){ b0v = bias2[col-128]; b1v = bias2[col-127]; }
        else { b0v = bias[col]; b1v = bias[col+1]; }
        float v00 = c[nt][0] + b0v, v01 = c[nt][1] + b1v;   // row r0
        float v10 = c[nt][2] + b0v, v11 = c[nt][3] + b1v;   // row r1
        if (mode == 1){
            v00 = silu_f(v00); v01 = silu_f(v01);
            v10 = silu_f(v10); v11 = silu_f(v11);
            if (r0 < M){
                __nv_bfloat16 h0 = __float2bfloat16_rn(v00), h1 = __float2bfloat16_rn(v01);
                u32 ph = (u32)__bfloat16_as_ushort(h0) | ((u32)__bfloat16_as_ushort(h1) << 16);
                *(u32*)(g_a1h + (long)r0*Ntot + col) = ph;
                __nv_bfloat16 l0 = __float2bfloat16_rn(v00 - __bfloat162float(h0));
                __nv_bfloat16 l1 = __float2bfloat16_rn(v01 - __bfloat162float(h1));
                u32 pl = (u32)__bfloat16_as_ushort(l0) | ((u32)__bfloat16_as_ushort(l1) << 16);
                *(u32*)(g_a1l + (long)r0*Ntot + col) = pl;
            }
            if (r1 < M){
                __nv_bfloat16 h0 = __float2bfloat16_rn(v10), h1 = __float2bfloat16_rn(v11);
                u32 ph = (u32)__bfloat16_as_ushort(h0) | ((u32)__bfloat16_as_ushort(h1) << 16);
                *(u32*)(g_a1h + (long)r1*Ntot + col) = ph;
                __nv_bfloat16 l0 = __float2bfloat16_rn(v10 - __bfloat162float(h0));
                __nv_bfloat16 l1 = __float2bfloat16_rn(v11 - __bfloat162float(h1));
                u32 pl = (u32)__bfloat16_as_ushort(l0) | ((u32)__bfloat16_as_ushort(l1) << 16);
                *(u32*)(g_a1l + (long)r1*Ntot + col) = pl;
            }
        } else {
            float* C = (osel == 0) ? g_so : (osel == 1) ? g_UV : (osel == 2) ? g_gate : Cext;
            if (r0 < M){ float2 v = make_float2(v00, v01); *(float2*)&C[(long)r0*Ntot + col] = v; }
            if (r1 < M){ float2 v = make_float2(v10, v11); *(float2*)&C[(long)r1*Ntot + col] = v; }
        }
    }
}

// ---------------- edge message pass (fp32, unchanged core) ----------------
__global__ __launch_bounds__(128) void k_edge(int l,
        const float* __restrict__ fw_, const float* __restrict__ fb_){
    const float* Wf = fw_ + l*ER*3*HH;
    const float* Bf = fb_ + l*3*HH;
    const float* nv_in  = (l == 1) ? g_nvB : g_nvA;
    float*       nv_out = (l == 1) ? g_nvA : g_nvB;
    int j = threadIdx.x;
    u64 wf0[ER/2], wf1[ER/2], wf2[ER/2];
#pragma unroll
    for (int k = 0; k < ER/2; k++){
        wf0[k] = f2pack(Wf[(2*k)*384 + j],       Wf[(2*k+1)*384 + j]);
        wf1[k] = f2pack(Wf[(2*k)*384 + 128 + j], Wf[(2*k+1)*384 + 128 + j]);
        wf2[k] = f2pack(Wf[(2*k)*384 + 256 + j], Wf[(2*k+1)*384 + 256 + j]);
    }
    float bf0 = Bf[j], bf1 = Bf[128+j], bf2 = Bf[256+j];
    const int NPB = 4;
    for (int ni = 0; ni < NPB; ni++){
        int n = blockIdx.x*NPB + ni;
        int s = g_off[n], e1 = g_off[n+1];
        float acc_s = 0.f, av0 = 0.f, av1 = 0.f, av2 = 0.f;
        for (int p = s; p < e1; p++){
            int src = g_psrc[p];
            float4 geo = g_pgeo[p];
            float fc = geo.w;
            u64 f0a = f2pack(bf0*fc, 0.f);
            u64 f1a = f2pack(bf1*fc, 0.f);
            u64 f2a = f2pack(bf2*fc, 0.f);
            const ulonglong2* r2 = (const ulonglong2*)&g_prbfc[p*RST];
#pragma unroll
            for (int q = 0; q < 5; q++){
                ulonglong2 rr = r2[q];
                f0a = f2fma(rr.x, wf0[2*q],   f0a);
                f0a = f2fma(rr.y, wf0[2*q+1], f0a);
                f1a = f2fma(rr.x, wf1[2*q],   f1a);
                f1a = f2fma(rr.y, wf1[2*q+1], f1a);
                f2a = f2fma(rr.x, wf2[2*q],   f2a);
                f2a = f2fma(rr.y, wf2[2*q+1], f2a);
            }
            const float* sb = &g_so[(long)src*384];
            float gsv = f2sum(f0a) * sb[j];
            float gev = f2sum(f1a) * sb[128 + j];
            float ms  = f2sum(f2a) * sb[256 + j];
            acc_s += ms;
            const float* nb = &nv_in[(long)src*384];
            av0 += nb[j      ]*gsv + gev*geo.x;
            av1 += nb[128 + j]*gsv + gev*geo.y;
            av2 += nb[256 + j]*gsv + gev*geo.z;
        }
        g_ns[n*128 + j] += acc_s;
        nv_out[(long)n*384 + j      ] = nv_in[(long)n*384 + j      ] + av0;
        nv_out[(long)n*384 + 128 + j] = nv_in[(long)n*384 + 128 + j] + av1;
        nv_out[(long)n*384 + 256 + j] = nv_in[(long)n*384 + 256 + j] + av2;
    }
}

// build upd-MLP input (||Vv|| | ns) directly as bf16 hi/lo into A0 [NN,256]
__global__ __launch_bounds__(128) void k_prep(){
    int j = threadIdx.x;
    const int NPB = 4;
    for (int ni = 0; ni < NPB; ni++){
        int n = blockIdx.x*NPB + ni;
        float V0 = g_UV[(long)(n*3+0)*256 + 128 + j];
        float V1 = g_UV[(long)(n*3+1)*256 + 128 + j];
        float V2 = g_UV[(long)(n*3+2)*256 + 128 + j];
        float nm = sqrtf(V0*V0 + V1*V1 + V2*V2);
        float sc = g_ns[n*128 + j];
        __nv_bfloat16 h;
        h = __float2bfloat16_rn(nm);
        g_a0h[(long)n*256 + j] = h;
        g_a0l[(long)n*256 + j] = __float2bfloat16_rn(nm - __bfloat162float(h));
        h = __float2bfloat16_rn(sc);
        g_a0h[(long)n*256 + 128 + j] = h;
        g_a0l[(long)n*256 + 128 + j] = __float2bfloat16_rn(sc - __bfloat162float(h));
    }
}

// apply gates
__global__ __launch_bounds__(128) void k_apply(int l){
    float* nv = (l == 1) ? g_nvA : g_nvB;
    int j = threadIdx.x;
    const int NPB = 4;
    for (int ni = 0; ni < NPB; ni++){
        int n = blockIdx.x*NPB + ni;
        float avv = g_gate[(long)n*384 + j];
        float asv = g_gate[(long)n*384 + 128 + j];
        float ass = g_gate[(long)n*384 + 256 + j];
        float U0 = g_UV[(long)(n*3+0)*256 + j];
        float U1 = g_UV[(long)(n*3+1)*256 + j];
        float U2 = g_UV[(long)(n*3+2)*256 + j];
        float V0 = g_UV[(long)(n*3+0)*256 + 128 + j];
        float V1 = g_UV[(long)(n*3+1)*256 + 128 + j];
        float V2 = g_UV[(long)(n*3+2)*256 + 128 + j];
        float duv = U0*V0 + U1*V1 + U2*V2;
        nv[(long)n*384 + j      ] += avv*U0;
        nv[(long)n*384 + 128 + j] += avv*U1;
        nv[(long)n*384 + 256 + j] += avv*U2;
        g_ns[n*128 + j] += asv*duv + ass;
    }
}

// ---------------- launch ----------------
extern "C" void kernel_launch(void* const* d_in, const int* in_sizes, int n_in,
                              void* d_out, int out_size){
    const int*   z         = (const int*)  d_in[0];
    const int*   edge      = (const int*)  d_in[1];
    const float* edge_diff = (const float*)d_in[2];
    const float* edge_dist = (const float*)d_in[3];
    const float* embed     = (const float*)d_in[4];
    const float* mfw = (const float*)d_in[5];
    const float* mfb = (const float*)d_in[6];
    const float* mw1 = (const float*)d_in[7];
    const float* mb1 = (const float*)d_in[8];
    const float* mw2 = (const float*)d_in[9];
    const float* mb2 = (const float*)d_in[10];
    const float* uUw = (const float*)d_in[11];
    const float* uUb = (const float*)d_in[12];
    const float* uVw = (const float*)d_in[13];
    const float* uVb = (const float*)d_in[14];
    const float* uw1 = (const float*)d_in[15];
    const float* ub1 = (const float*)d_in[16];
    const float* uw2 = (const float*)d_in[17];
    const float* ub2 = (const float*)d_in[18];
    const float* rw1 = (const float*)d_in[19];
    const float* rb1 = (const float*)d_in[20];
    const float* rw2 = (const float*)d_in[21];
    const float* rb2 = (const float*)d_in[22];
    float* out = (float*)d_out;

    const int GM  = (NN + 63)/64;        // 157
    const int GUV = (NN*3 + 63)/64;      // 469

    // 1: pack msg W1 (needed by launch #4, which ncu profiles)
    { long tot = 3L*8*128*4; k_pack<<<(int)((tot+255)/256),256>>>(mw1, 0, 3, 128, 128, 0, OFF_MSGW1); }
    // 2
    k_init_ns<<<(NN*HH + 255)/256, 256>>>(z, embed);
    // 3
    k_cvt_a<<<(NN*HH + 255)/256, 256>>>(0, (long)NN*HH);
    // 4: first tensor GEMM (profiled)
    k_mma<<<dim3(GM,1), 128>>>(OFF_MSGW1, NN, 128, 128, 0, 1, 0, mb1, 0, 0);
    // remaining packs + setup
    { long tot = 3L*8*384*4;  k_pack<<<(int)((tot+255)/256),256>>>(mw2, 0,   3, 128, 384, 0,   OFF_MSGW2); }
    { long tot = 3L*8*256*4;  k_pack<<<(int)((tot+255)/256),256>>>(uUw, uVw, 3, 128, 256, 128, OFF_UVW); }
    { long tot = 3L*16*128*4; k_pack<<<(int)((tot+255)/256),256>>>(uw1, 0,   3, 256, 128, 0,   OFF_UPDW1); }
    { long tot = 3L*8*384*4;  k_pack<<<(int)((tot+255)/256),256>>>(uw2, 0,   3, 128, 384, 0,   OFF_UPDW2); }
    { long tot = 1L*8*128*4;  k_pack<<<(int)((tot+255)/256),256>>>(rw1, 0,   1, 128, 128, 0,   OFF_ROW1); }
    { long tot = 1L*8*128*4;  k_pack<<<(int)((tot+255)/256),256>>>(rw2, 0,   1, 128, 128, 0,   OFF_ROW2); }
    k_zero_nv<<<(NN*3*HH + 255)/256, 256>>>();
    k_zero_deg<<<(NN + 255)/256, 256>>>();
    k_count<<<(NE + 255)/256, 256>>>(edge);
    k_scan<<<1, 1024>>>();
    k_scatter<<<(NE + 255)/256, 256>>>(edge);
    k_geom<<<(NE + 255)/256, 256>>>(edge, edge_dist, edge_diff);

    for (int l = 0; l < 3; l++){
        if (l > 0){
            k_cvt_a<<<(NN*HH + 255)/256, 256>>>(0, (long)NN*HH);
            k_mma<<<dim3(GM,1), 128>>>(OFF_MSGW1 + l*4096L, NN, 128, 128, 0, 1, 0, mb1 + l*128, 0, 0);
        }
        k_mma<<<dim3(GM,3), 128>>>(OFF_MSGW2 + l*12288L, NN, 128, 384, 1, 0, 0, mb2 + l*384, 0, 0);
        k_edge<<<NN/4, 128>>>(l, mfw, mfb);
        // uv: input nv buffer of this layer
        k_cvt_a<<<(NN*3*HH + 255)/256, 256>>>((l == 1) ? 1 : 2, (long)NN*3*HH);
        k_mma<<<dim3(GUV,2), 128>>>(OFF_UVW + l*8192L, NN*3, 128, 256, 0, 0, 1, uUb + l*128, uVb + l*128, 0);
        k_prep<<<NN/4, 128>>>();
        k_mma<<<dim3(GM,1), 128>>>(OFF_UPDW1 + l*8192L, NN, 256, 128, 0, 1, 0, ub1 + l*128, 0, 0);
        k_mma<<<dim3(GM,3), 128>>>(OFF_UPDW2 + l*12288L, NN, 128, 384, 1, 0, 2, ub2 + l*384, 0, 0);
        k_apply<<<NN/4, 128>>>(l);
    }
    // readout
    k_cvt_a<<<(NN*HH + 255)/256, 256>>>(0, (long)NN*HH);
    k_mma<<<dim3(GM,1), 128>>>(OFF_ROW1, NN, 128, 128, 0, 1, 0, rb1, 0, 0);
    k_mma<<<dim3(GM,1), 128>>>(OFF_ROW2, NN, 128, 128, 1, 0, 3, rb2, 0, out);
}

// round 7
// speedup vs baseline: 1.3154x; 1.0056x over previous
#include <cuda_runtime.h>
#include <cuda_bf16.h>
#include <math.h>

#define NN 10000
#define NE 160000
#define HH 128
#define ER 20
#define RST 24
#define CUTOFF_F 5.0f
#define PI_F 3.14159265358979323846f

typedef unsigned long long u64;
typedef unsigned int u32;

// ---------------- device scratch ----------------
__device__ float g_ns [NN*HH];
__device__ float g_nvA[NN*3*HH];
__device__ float g_nvB[NN*3*HH];
__device__ float g_so [NN*3*HH];
__device__ float g_UV [NN*3*256];
__device__ float g_gate[NN*384];
__device__ __align__(16) float g_prbfc[NE*RST];
__device__ float4 g_pgeo[NE];
__device__ int   g_psrc[NE];
__device__ int   g_deg [NN];
__device__ int   g_off [NN+1];
__device__ int   g_cur [NN];
__device__ int   g_perm[NE];
__device__ __nv_bfloat16 g_a0h[NN*3*256];
__device__ __nv_bfloat16 g_a0l[NN*3*256];
__device__ __nv_bfloat16 g_a1h[NN*HH];
__device__ __nv_bfloat16 g_a1l[NN*HH];
#define WP_TOTAL 143360
__device__ u64 g_wph[WP_TOTAL];
__device__ u64 g_wpl[WP_TOTAL];
#define OFF_MSGW1 0L
#define OFF_MSGW2 12288L
#define OFF_UVW   49152L
#define OFF_UPDW1 73728L
#define OFF_UPDW2 98304L
#define OFF_ROW1  135168L
#define OFF_ROW2  139264L

__device__ __forceinline__ float silu_f(float x){
    return x * (1.0f / (1.0f + __expf(-x)));
}
__device__ __forceinline__ u64 f2fma(u64 a, u64 b, u64 c){
    u64 d; asm("fma.rn.f32x2 %0, %1, %2, %3;" : "=l"(d) : "l"(a), "l"(b), "l"(c)); return d;
}
__device__ __forceinline__ u64 f2pack(float lo, float hi){
    u64 d; asm("mov.b64 %0, {%1, %2};" : "=l"(d) : "f"(lo), "f"(hi)); return d;
}
__device__ __forceinline__ float f2sum(u64 a){
    float x, y; asm("mov.b64 {%0, %1}, %2;" : "=f"(x), "=f"(y) : "l"(a)); return x + y;
}
__device__ __forceinline__ void mma16816(float* c, u32 a0,u32 a1,u32 a2,u32 a3, u32 b0,u32 b1){
    asm volatile("mma.sync.aligned.m16n8k16.row.col.f32.bf16.bf16.f32 "
        "{%0,%1,%2,%3}, {%4,%5,%6,%7}, {%8,%9}, {%0,%1,%2,%3};"
        : "+f"(c[0]),"+f"(c[1]),"+f"(c[2]),"+f"(c[3])
        : "r"(a0),"r"(a1),"r"(a2),"r"(a3),"r"(b0),"r"(b1));
}
__device__ __forceinline__ void bf16hl(float v, __nv_bfloat16* H, __nv_bfloat16* L, long idx){
    __nv_bfloat16 h = __float2bfloat16_rn(v);
    H[idx] = h;
    L[idx] = __float2bfloat16_rn(v - __bfloat162float(h));
}

// ---------------- setup kernels ----------------
__global__ void k_init_ns(const int* __restrict__ z, const float* __restrict__ embed){
    int i = blockIdx.x*blockDim.x + threadIdx.x;
    if (i < NN*HH){ int n = i >> 7; int j = i & 127; g_ns[i] = embed[z[n]*HH + j]; }
}
__global__ void k_zero_nv(){
    int i = blockIdx.x*blockDim.x + threadIdx.x;
    if (i < NN*3*HH){
        g_nvA[i] = 0.0f;
        // nv bf16 view for layer-0 uv gemm gets written by k_edge; nothing needed here
    }
}
__global__ void k_zero_deg(){
    int i = blockIdx.x*blockDim.x + threadIdx.x;
    if (i < NN) g_deg[i] = 0;
}
__global__ void k_count(const int* __restrict__ edge){
    int e = blockIdx.x*blockDim.x + threadIdx.x;
    if (e < NE) atomicAdd(&g_deg[edge[2*e]], 1);
}
__global__ void k_scan(){
    __shared__ int sm[1024];
    __shared__ int base_s;
    int t = threadIdx.x;
    if (t == 0){ base_s = 0; g_off[0] = 0; }
    __syncthreads();
    for (int c0 = 0; c0 < NN; c0 += 1024){
        int i = c0 + t;
        int v = (i < NN) ? g_deg[i] : 0;
        sm[t] = v;
        __syncthreads();
        for (int ofs = 1; ofs < 1024; ofs <<= 1){
            int tv = (t >= ofs) ? sm[t-ofs] : 0;
            __syncthreads();
            sm[t] += tv;
            __syncthreads();
        }
        int inc = sm[t];
        int b = base_s;
        if (i < NN){ g_off[i+1] = b + inc; g_cur[i] = b + inc - v; }
        __syncthreads();
        if (t == 1023) base_s = b + sm[1023];
        __syncthreads();
    }
}
__global__ void k_scatter(const int* __restrict__ edge){
    int e = blockIdx.x*blockDim.x + threadIdx.x;
    if (e < NE){ int dst = edge[2*e]; int p = atomicAdd(&g_cur[dst], 1); g_perm[p] = e; }
}
__global__ void k_geom(const int* __restrict__ edge,
                       const float* __restrict__ dist, const float* __restrict__ diff){
    int p = blockIdx.x*blockDim.x + threadIdx.x;
    if (p >= NE) return;
    int e = g_perm[p];
    g_psrc[p] = edge[2*e + 1];
    float d = dist[e];
    float invd = 1.0f / d;
    float fc = (d < CUTOFF_F) ? 0.5f*(cosf(PI_F*d*(1.0f/CUTOFF_F)) + 1.0f) : 0.0f;
    g_pgeo[p] = make_float4(diff[3*e]*invd, diff[3*e+1]*invd, diff[3*e+2]*invd, fc);
    float s = fc * invd;
#pragma unroll
    for (int k = 0; k < ER; k++)
        g_prbfc[p*RST + k] = sinf(d * (float)(k+1) * (PI_F/CUTOFF_F)) * s;
#pragma unroll
    for (int k = ER; k < RST; k++) g_prbfc[p*RST + k] = 0.0f;
}

__global__ void k_pack(const float* __restrict__ src, const float* __restrict__ src2,
                       int L, int K, int N, int N1, long dstoff){
    long per = (long)(K/16)*N*4;
    long tot = per * L;
    long i = (long)blockIdx.x*blockDim.x + threadIdx.x;
    if (i >= tot) return;
    int l = (int)(i / per); long r = i % per;
    int m = (int)(r & 3); long r2 = r >> 2;
    int n = (int)(r2 % N); int s = (int)(r2 / N);
    int k0 = s*16 + 2*m;
    const float* S; int nn, Nw;
    if (src2 && n >= N1){ S = src2 + (long)l*K*(N-N1); nn = n - N1; Nw = N - N1; }
    else if (src2)      { S = src  + (long)l*K*N1;     nn = n;      Nw = N1; }
    else                { S = src  + (long)l*K*N;      nn = n;      Nw = N; }
    float w0 = S[(long)(k0  )*Nw + nn];
    float w1 = S[(long)(k0+1)*Nw + nn];
    float w8 = S[(long)(k0+8)*Nw + nn];
    float w9 = S[(long)(k0+9)*Nw + nn];
    __nv_bfloat16 h0 = __float2bfloat16_rn(w0), h1 = __float2bfloat16_rn(w1);
    __nv_bfloat16 h8 = __float2bfloat16_rn(w8), h9 = __float2bfloat16_rn(w9);
    u32 hlo = (u32)__bfloat16_as_ushort(h0) | ((u32)__bfloat16_as_ushort(h1) << 16);
    u32 hhi = (u32)__bfloat16_as_ushort(h8) | ((u32)__bfloat16_as_ushort(h9) << 16);
    g_wph[dstoff + i] = (u64)hlo | ((u64)hhi << 32);
    __nv_bfloat16 l0 = __float2bfloat16_rn(w0 - __bfloat162float(h0));
    __nv_bfloat16 l1 = __float2bfloat16_rn(w1 - __bfloat162float(h1));
    __nv_bfloat16 l8 = __float2bfloat16_rn(w8 - __bfloat162float(h8));
    __nv_bfloat16 l9 = __float2bfloat16_rn(w9 - __bfloat162float(h9));
    u32 llo = (u32)__bfloat16_as_ushort(l0) | ((u32)__bfloat16_as_ushort(l1) << 16);
    u32 lhi = (u32)__bfloat16_as_ushort(l8) | ((u32)__bfloat16_as_ushort(l9) << 16);
    g_wpl[dstoff + i] = (u64)llo | ((u64)lhi << 32);
}

__global__ void k_cvt_a(long total){
    long i = (long)blockIdx.x*blockDim.x + threadIdx.x;
    if (i >= total) return;
    bf16hl(g_ns[i], g_a0h, g_a0l, i);
}

// ---------------- tensor-core GEMM ----------------
// 256 thr = 8 warps; block tile 32 rows x 128 cols; warp tile 16 x 32.
__global__ __launch_bounds__(256) void k_mma(
        long woff, int M, int K, int Ntot, int asel, int mode, int osel,
        const float* __restrict__ bias, const float* __restrict__ bias2,
        float* __restrict__ Cext){
    int tid = threadIdx.x;
    int lane = tid & 31, w = tid >> 5;
    int mw = w & 1, nw = w >> 1;
    int m0 = blockIdx.x*32 + mw*16;
    int nbase = blockIdx.y*128 + nw*32;
    const __nv_bfloat16* Ah = asel ? g_a1h : g_a0h;
    const __nv_bfloat16* Al = asel ? g_a1l : g_a0l;
    int r0 = m0 + (lane >> 2);
    int r1 = r0 + 8;
    int r0c = r0 < M ? r0 : M-1;
    int r1c = r1 < M ? r1 : M-1;
    int kofs = (lane & 3)*2;
    const u64* WH = g_wph + woff;
    const u64* WL = g_wpl + woff;
    float c[4][4];
#pragma unroll
    for (int nt = 0; nt < 4; nt++){ c[nt][0]=0.f; c[nt][1]=0.f; c[nt][2]=0.f; c[nt][3]=0.f; }
    int nsteps = K >> 4;
    for (int s = 0; s < nsteps; s++){
        int k0 = s*16 + kofs;
        const __nv_bfloat16* ph0 = Ah + (long)r0c*K + k0;
        const __nv_bfloat16* ph1 = Ah + (long)r1c*K + k0;
        const __nv_bfloat16* pl0 = Al + (long)r0c*K + k0;
        const __nv_bfloat16* pl1 = Al + (long)r1c*K + k0;
        u32 ah0 = *(const u32*)(ph0);
        u32 ah1 = *(const u32*)(ph1);
        u32 ah2 = *(const u32*)(ph0 + 8);
        u32 ah3 = *(const u32*)(ph1 + 8);
        u32 al0 = *(const u32*)(pl0);
        u32 al1 = *(const u32*)(pl1);
        u32 al2 = *(const u32*)(pl0 + 8);
        u32 al3 = *(const u32*)(pl1 + 8);
        long wrow = ((long)s*Ntot + nbase)*4 + (lane & 3);
#pragma unroll
        for (int nt = 0; nt < 4; nt++){
            long wi = wrow + (long)(nt*8 + (lane >> 2))*4;
            u64 wh = WH[wi];
            u64 wl = WL[wi];
            u32 bh0 = (u32)wh, bh1 = (u32)(wh >> 32);
            u32 bl0 = (u32)wl, bl1 = (u32)(wl >> 32);
            mma16816(c[nt], ah0, ah1, ah2, ah3, bh0, bh1);
            mma16816(c[nt], al0, al1, al2, al3, bh0, bh1);
            mma16816(c[nt], ah0, ah1, ah2, ah3, bl0, bl1);
        }
    }
    int colq = (lane & 3)*2;
#pragma unroll
    for (int nt = 0; nt < 4; nt++){
        int col = nbase + nt*8 + colq;
        float b0v, b1v;
        if (bias2 != 0 && col >= 128){ b0v = bias2[col-128]; b1v = bias2[col-127]; }
        else { b0v = bias[col]; b1v = bias[col+1]; }
        float v00 = c[nt][0] + b0v, v01 = c[nt][1] + b1v;
        float v10 = c[nt][2] + b0v, v11 = c[nt][3] + b1v;
        if (mode == 1){
            v00 = silu_f(v00); v01 = silu_f(v01);
            v10 = silu_f(v10); v11 = silu_f(v11);
            if (r0 < M){
                __nv_bfloat16 h0 = __float2bfloat16_rn(v00), h1 = __float2bfloat16_rn(v01);
                u32 ph = (u32)__bfloat16_as_ushort(h0) | ((u32)__bfloat16_as_ushort(h1) << 16);
                *(u32*)(g_a1h + (long)r0*Ntot + col) = ph;
                __nv_bfloat16 l0 = __float2bfloat16_rn(v00 - __bfloat162float(h0));
                __nv_bfloat16 l1 = __float2bfloat16_rn(v01 - __bfloat162float(h1));
                u32 pl = (u32)__bfloat16_as_ushort(l0) | ((u32)__bfloat16_as_ushort(l1) << 16);
                *(u32*)(g_a1l + (long)r0*Ntot + col) = pl;
            }
            if (r1 < M){
                __nv_bfloat16 h0 = __float2bfloat16_rn(v10), h1 = __float2bfloat16_rn(v11);
                u32 ph = (u32)__bfloat16_as_ushort(h0) | ((u32)__bfloat16_as_ushort(h1) << 16);
                *(u32*)(g_a1h + (long)r1*Ntot + col) = ph;
                __nv_bfloat16 l0 = __float2bfloat16_rn(v10 - __bfloat162float(h0));
                __nv_bfloat16 l1 = __float2bfloat16_rn(v11 - __bfloat162float(h1));
                u32 pl = (u32)__bfloat16_as_ushort(l0) | ((u32)__bfloat16_as_ushort(l1) << 16);
                *(u32*)(g_a1l + (long)r1*Ntot + col) = pl;
            }
        } else {
            float* C = (osel == 0) ? g_so : (osel == 1) ? g_UV : (osel == 2) ? g_gate : Cext;
            if (r0 < M){ float2 v = make_float2(v00, v01); *(float2*)&C[(long)r0*Ntot + col] = v; }
            if (r1 < M){ float2 v = make_float2(v10, v11); *(float2*)&C[(long)r1*Ntot + col] = v; }
        }
    }
}

// ---------------- edge message pass (fused bf16 output of nv_out) ----------------
__global__ __launch_bounds__(128) void k_edge(int l,
        const float* __restrict__ fw_, const float* __restrict__ fb_){
    const float* Wf = fw_ + l*ER*3*HH;
    const float* Bf = fb_ + l*3*HH;
    const float* nv_in  = (l == 1) ? g_nvB : g_nvA;
    float*       nv_out = (l == 1) ? g_nvA : g_nvB;
    int j = threadIdx.x;
    u64 wf0[ER/2], wf1[ER/2], wf2[ER/2];
#pragma unroll
    for (int k = 0; k < ER/2; k++){
        wf0[k] = f2pack(Wf[(2*k)*384 + j],       Wf[(2*k+1)*384 + j]);
        wf1[k] = f2pack(Wf[(2*k)*384 + 128 + j], Wf[(2*k+1)*384 + 128 + j]);
        wf2[k] = f2pack(Wf[(2*k)*384 + 256 + j], Wf[(2*k+1)*384 + 256 + j]);
    }
    float bf0 = Bf[j], bf1 = Bf[128+j], bf2 = Bf[256+j];
    const int NPB = 4;
    for (int ni = 0; ni < NPB; ni++){
        int n = blockIdx.x*NPB + ni;
        int s = g_off[n], e1 = g_off[n+1];
        float acc_s = 0.f, av0 = 0.f, av1 = 0.f, av2 = 0.f;
        for (int p = s; p < e1; p++){
            int src = g_psrc[p];
            float4 geo = g_pgeo[p];
            float fc = geo.w;
            u64 f0a = f2pack(bf0*fc, 0.f);
            u64 f1a = f2pack(bf1*fc, 0.f);
            u64 f2a = f2pack(bf2*fc, 0.f);
            const ulonglong2* r2 = (const ulonglong2*)&g_prbfc[p*RST];
#pragma unroll
            for (int q = 0; q < 5; q++){
                ulonglong2 rr = r2[q];
                f0a = f2fma(rr.x, wf0[2*q],   f0a);
                f0a = f2fma(rr.y, wf0[2*q+1], f0a);
                f1a = f2fma(rr.x, wf1[2*q],   f1a);
                f1a = f2fma(rr.y, wf1[2*q+1], f1a);
                f2a = f2fma(rr.x, wf2[2*q],   f2a);
                f2a = f2fma(rr.y, wf2[2*q+1], f2a);
            }
            const float* sb = &g_so[(long)src*384];
            float gsv = f2sum(f0a) * sb[j];
            float gev = f2sum(f1a) * sb[128 + j];
            float ms  = f2sum(f2a) * sb[256 + j];
            acc_s += ms;
            const float* nb = &nv_in[(long)src*384];
            av0 += nb[j      ]*gsv + gev*geo.x;
            av1 += nb[128 + j]*gsv + gev*geo.y;
            av2 += nb[256 + j]*gsv + gev*geo.z;
        }
        g_ns[n*128 + j] += acc_s;
        float o0 = nv_in[(long)n*384 + j      ] + av0;
        float o1 = nv_in[(long)n*384 + 128 + j] + av1;
        float o2 = nv_in[(long)n*384 + 256 + j] + av2;
        nv_out[(long)n*384 + j      ] = o0;
        nv_out[(long)n*384 + 128 + j] = o1;
        nv_out[(long)n*384 + 256 + j] = o2;
        bf16hl(o0, g_a0h, g_a0l, (long)n*384 + j);
        bf16hl(o1, g_a0h, g_a0l, (long)n*384 + 128 + j);
        bf16hl(o2, g_a0h, g_a0l, (long)n*384 + 256 + j);
    }
}

// build upd-MLP input (||Vv|| | ns) as bf16 hi/lo into A0 [NN,256]
__global__ __launch_bounds__(128) void k_prep(){
    int j = threadIdx.x;
    const int NPB = 4;
    for (int ni = 0; ni < NPB; ni++){
        int n = blockIdx.x*NPB + ni;
        float V0 = g_UV[(long)(n*3+0)*256 + 128 + j];
        float V1 = g_UV[(long)(n*3+1)*256 + 128 + j];
        float V2 = g_UV[(long)(n*3+2)*256 + 128 + j];
        float nm = sqrtf(V0*V0 + V1*V1 + V2*V2);
        bf16hl(nm, g_a0h, g_a0l, (long)n*256 + j);
        bf16hl(g_ns[n*128 + j], g_a0h, g_a0l, (long)n*256 + 128 + j);
    }
}

// apply gates; fused bf16 output of updated ns (next layer msg mlp / readout input)
__global__ __launch_bounds__(128) void k_apply(int l){
    float* nv = (l == 1) ? g_nvA : g_nvB;
    int j = threadIdx.x;
    const int NPB = 4;
    for (int ni = 0; ni < NPB; ni++){
        int n = blockIdx.x*NPB + ni;
        float avv = g_gate[(long)n*384 + j];
        float asv = g_gate[(long)n*384 + 128 + j];
        float ass = g_gate[(long)n*384 + 256 + j];
        float U0 = g_UV[(long)(n*3+0)*256 + j];
        float U1 = g_UV[(long)(n*3+1)*256 + j];
        float U2 = g_UV[(long)(n*3+2)*256 + j];
        float V0 = g_UV[(long)(n*3+0)*256 + 128 + j];
        float V1 = g_UV[(long)(n*3+1)*256 + 128 + j];
        float V2 = g_UV[(long)(n*3+2)*256 + 128 + j];
        float duv = U0*V0 + U1*V1 + U2*V2;
        nv[(long)n*384 + j      ] += avv*U0;
        nv[(long)n*384 + 128 + j] += avv*U1;
        nv[(long)n*384 + 256 + j] += avv*U2;
        float ns_new = g_ns[n*128 + j] + asv*duv + ass;
        g_ns[n*128 + j] = ns_new;
        bf16hl(ns_new, g_a0h, g_a0l, (long)n*128 + j);
    }
}

// ---------------- launch ----------------
extern "C" void kernel_launch(void* const* d_in, const int* in_sizes, int n_in,
                              void* d_out, int out_size){
    const int*   z         = (const int*)  d_in[0];
    const int*   edge      = (const int*)  d_in[1];
    const float* edge_diff = (const float*)d_in[2];
    const float* edge_dist = (const float*)d_in[3];
    const float* embed     = (const float*)d_in[4];
    const float* mfw = (const float*)d_in[5];
    const float* mfb = (const float*)d_in[6];
    const float* mw1 = (const float*)d_in[7];
    const float* mb1 = (const float*)d_in[8];
    const float* mw2 = (const float*)d_in[9];
    const float* mb2 = (const float*)d_in[10];
    const float* uUw = (const float*)d_in[11];
    const float* uUb = (const float*)d_in[12];
    const float* uVw = (const float*)d_in[13];
    const float* uVb = (const float*)d_in[14];
    const float* uw1 = (const float*)d_in[15];
    const float* ub1 = (const float*)d_in[16];
    const float* uw2 = (const float*)d_in[17];
    const float* ub2 = (const float*)d_in[18];
    const float* rw1 = (const float*)d_in[19];
    const float* rb1 = (const float*)d_in[20];
    const float* rw2 = (const float*)d_in[21];
    const float* rb2 = (const float*)d_in[22];
    float* out = (float*)d_out;

    const int GM  = (NN + 31)/32;        // 313
    const int GUV = (NN*3 + 31)/32;      // 938

    // launches 1-3, then #4 = k_mma (profiled)
    { long tot = 3L*8*128*4; k_pack<<<(int)((tot+255)/256),256>>>(mw1, 0, 3, 128, 128, 0, OFF_MSGW1); }
    k_init_ns<<<(NN*HH + 255)/256, 256>>>(z, embed);
    k_cvt_a<<<(NN*HH + 255)/256, 256>>>((long)NN*HH);
    k_mma<<<dim3(GM,1), 256>>>(OFF_MSGW1, NN, 128, 128, 0, 1, 0, mb1, 0, 0);

    { long tot = 3L*8*384*4;  k_pack<<<(int)((tot+255)/256),256>>>(mw2, 0,   3, 128, 384, 0,   OFF_MSGW2); }
    { long tot = 3L*8*256*4;  k_pack<<<(int)((tot+255)/256),256>>>(uUw, uVw, 3, 128, 256, 128, OFF_UVW); }
    { long tot = 3L*16*128*4; k_pack<<<(int)((tot+255)/256),256>>>(uw1, 0,   3, 256, 128, 0,   OFF_UPDW1); }
    { long tot = 3L*8*384*4;  k_pack<<<(int)((tot+255)/256),256>>>(uw2, 0,   3, 128, 384, 0,   OFF_UPDW2); }
    { long tot = 1L*8*128*4;  k_pack<<<(int)((tot+255)/256),256>>>(rw1, 0,   1, 128, 128, 0,   OFF_ROW1); }
    { long tot = 1L*8*128*4;  k_pack<<<(int)((tot+255)/256),256>>>(rw2, 0,   1, 128, 128, 0,   OFF_ROW2); }
    k_zero_nv<<<(NN*3*HH + 255)/256, 256>>>();
    k_zero_deg<<<(NN + 255)/256, 256>>>();
    k_count<<<(NE + 255)/256, 256>>>(edge);
    k_scan<<<1, 1024>>>();
    k_scatter<<<(NE + 255)/256, 256>>>(edge);
    k_geom<<<(NE + 255)/256, 256>>>(edge, edge_dist, edge_diff);

    for (int l = 0; l < 3; l++){
        if (l > 0)
            k_mma<<<dim3(GM,1), 256>>>(OFF_MSGW1 + l*4096L, NN, 128, 128, 0, 1, 0, mb1 + l*128, 0, 0);
        k_mma<<<dim3(GM,3), 256>>>(OFF_MSGW2 + l*12288L, NN, 128, 384, 1, 0, 0, mb2 + l*384, 0, 0);
        k_edge<<<NN/4, 128>>>(l, mfw, mfb);           // also emits bf16(nv_out) -> A0
        k_mma<<<dim3(GUV,2), 256>>>(OFF_UVW + l*8192L, NN*3, 128, 256, 0, 0, 1, uUb + l*128, uVb + l*128, 0);
        k_prep<<<NN/4, 128>>>();
        k_mma<<<dim3(GM,1), 256>>>(OFF_UPDW1 + l*8192L, NN, 256, 128, 0, 1, 0, ub1 + l*128, 0, 0);
        k_mma<<<dim3(GM,3), 256>>>(OFF_UPDW2 + l*12288L, NN, 128, 384, 1, 0, 2, ub2 + l*384, 0, 0);
        k_apply<<<NN/4, 128>>>(l);                     // also emits bf16(ns) -> A0
    }
    k_mma<<<dim3(GM,1), 256>>>(OFF_ROW1, NN, 128, 128, 0, 1, 0, rb1, 0, 0);
    k_mma<<<dim3(GM,1), 256>>>(OFF_ROW2, NN, 128, 128, 1, 0, 3, rb2, 0, out);
}